// round 16
// baseline (speedup 1.0000x reference)
#include <cuda_runtime.h>
#include <cuda_fp16.h>
#include <math.h>
#include <stdint.h>

#define SEQ 4096
#define HID 1024
#define NH  16
#define HD  64

// Scratch (allocation-free rule: __device__ globals), all fp16
__device__ __half g_Xh[SEQ * HID];
__device__ __half g_Wqh[HID * HID];
__device__ __half g_Wkh[HID * HID];
__device__ __half g_Wvh[HID * HID];
__device__ __half g_Woh[HID * HID];
__device__ __half g_Qh[SEQ * HID];
__device__ __half g_Kh[SEQ * HID];
__device__ __half g_Vth[SEQ * HID];   // per-head transposed V: [h][d][s]
__device__ __half g_Ch[SEQ * HID];

// ---------------------------------------------------------------------------
// helpers
// ---------------------------------------------------------------------------
__device__ __forceinline__ uint32_t sptr(const void* p) {
    return (uint32_t)__cvta_generic_to_shared(p);
}
#define CPA16(dst, src) \
    asm volatile("cp.async.cg.shared.global [%0], [%1], 16;" :: "r"(dst), "l"(src))
#define CPC() asm volatile("cp.async.commit_group;")
#define CPW(N) asm volatile("cp.async.wait_group %0;" :: "n"(N))

#define LDSM4(r0, r1, r2, r3, addr) \
    asm volatile("ldmatrix.sync.aligned.m8n8.x4.shared.b16 {%0,%1,%2,%3}, [%4];" \
                 : "=r"(r0), "=r"(r1), "=r"(r2), "=r"(r3) : "r"(addr))

#define EX2F16X2(d, a) \
    asm volatile("ex2.approx.f16x2 %0, %1;" : "=r"(d) : "r"(a))

__device__ __forceinline__ void mma_h(float (&d)[4], uint32_t a0, uint32_t a1,
                                      uint32_t a2, uint32_t a3,
                                      uint32_t b0, uint32_t b1) {
    asm volatile(
        "mma.sync.aligned.m16n8k16.row.col.f32.f16.f16.f32 "
        "{%0,%1,%2,%3}, {%4,%5,%6,%7}, {%8,%9}, {%0,%1,%2,%3};\n"
        : "+f"(d[0]), "+f"(d[1]), "+f"(d[2]), "+f"(d[3])
        : "r"(a0), "r"(a1), "r"(a2), "r"(a3), "r"(b0), "r"(b1));
}

__device__ __forceinline__ uint32_t packh2(float lo, float hi) {
    __half2 h = __floats2half2_rn(lo, hi);
    return *reinterpret_cast<uint32_t*>(&h);
}

// scale/log2e folded into Q at projection time: S*scale*log2e == (Q*c)K^T
#define SLOG2E 0.18033688011112042f   // 0.125 * log2(e)

// ---------------------------------------------------------------------------
// f32 -> fp16 pack, all 5 tensors in one launch.
// ---------------------------------------------------------------------------
__global__ void pack_all_kernel(const float4* __restrict__ X, __half* __restrict__ Xh,
                                const float4* __restrict__ W0, __half* __restrict__ W0h,
                                const float4* __restrict__ W1, __half* __restrict__ W1h,
                                const float4* __restrict__ W2, __half* __restrict__ W2h,
                                const float4* __restrict__ W3, __half* __restrict__ W3h) {
    int b = blockIdx.x;
    const float4* src;
    __half* dst;
    int off;
    if (b < 4096)      { src = X;  dst = Xh;  off = b * 256; }
    else if (b < 5120) { src = W0; dst = W0h; off = (b - 4096) * 256; }
    else if (b < 6144) { src = W1; dst = W1h; off = (b - 5120) * 256; }
    else if (b < 7168) { src = W2; dst = W2h; off = (b - 6144) * 256; }
    else               { src = W3; dst = W3h; off = (b - 7168) * 256; }
    int i = off + threadIdx.x;
    float4 v = src[i];
    uint2 o;
    o.x = packh2(v.x, v.y);
    o.y = packh2(v.z, v.w);
    *(uint2*)&dst[i * 4] = o;
}

// ===========================================================================
// Shared GEMM machinery (round 11, proven): BM=BN=128, BK=64 halves,
// 256 thr = 8 warps (4m x 2n), 2-stage cp.async pipeline, ldmatrix.x4.
// ===========================================================================
struct GemmCore {
    const __half* A;
    const __half* B;
    int rowBase, colBase, K;
    uint32_t sA[2], sB[2];
    int tid, lane, w, wm, wn;

    __device__ __forceinline__ void stage(int k0, int buf) {
#pragma unroll
        for (int t = 0; t < 8; t++) {
            int i = tid + t * 256;
            int mat = i >> 10;
            int r = (i >> 3) & 127;
            int ch = i & 7;
            const __half* src = mat ? &B[(colBase + r) * K + k0 + ch * 8]
                                    : &A[(rowBase + r) * K + k0 + ch * 8];
            uint32_t d = (mat ? sB[buf] : sA[buf]) + (r * 72 + ch * 8) * 2;
            CPA16(d, src);
        }
    }

    __device__ __forceinline__ void compute(int buf, float (*acc)[4]) {
        const uint32_t sa = sA[buf], sb = sB[buf];
        const int rA = (lane & 7) + ((lane >> 3) & 1) * 8;
        const int cA = (lane >> 4) * 8;
        const int rB = (lane & 7) + (lane >> 4) * 8;
        const int cB = ((lane >> 3) & 1) * 8;
#pragma unroll
        for (int kg = 0; kg < 4; kg++) {
            uint32_t a[2][4];
#pragma unroll
            for (int mt = 0; mt < 2; mt++) {
                uint32_t ad = sa + ((wm * 32 + mt * 16 + rA) * 72 + kg * 16 + cA) * 2;
                LDSM4(a[mt][0], a[mt][1], a[mt][2], a[mt][3], ad);
            }
#pragma unroll
            for (int p = 0; p < 4; p++) {
                uint32_t b0, b1, b2, b3;
                uint32_t bd = sb + ((wn * 64 + p * 16 + rB) * 72 + kg * 16 + cB) * 2;
                LDSM4(b0, b1, b2, b3, bd);
                mma_h(acc[2 * p],     a[0][0], a[0][1], a[0][2], a[0][3], b0, b1);
                mma_h(acc[2 * p + 1], a[0][0], a[0][1], a[0][2], a[0][3], b2, b3);
                mma_h(acc[8 + 2 * p],     a[1][0], a[1][1], a[1][2], a[1][3], b0, b1);
                mma_h(acc[8 + 2 * p + 1], a[1][0], a[1][1], a[1][2], a[1][3], b2, b3);
            }
        }
    }
};

// ---------------------------------------------------------------------------
// Fused QKV GEMM. grid (24, 32): ct<8 -> Q (RoPE + scale fold), ct<16 -> K
// (RoPE), else V (written TRANSPOSED per head straight to Vt[h][d][s] via an
// in-smem 128x128 transpose — kills the separate transpose kernel and V's
// gmem round trip).
// ---------------------------------------------------------------------------
__global__ __launch_bounds__(256, 2)
void qkv_gemm(const __half* __restrict__ Xh,
              const __half* __restrict__ Wq, const __half* __restrict__ Wk,
              const __half* __restrict__ Wv, const int* __restrict__ pos,
              __half* __restrict__ Qh, __half* __restrict__ Kh,
              __half* __restrict__ Vt) {
    extern __shared__ char smem[];
    const int ct = blockIdx.x;
    const int wsel = ct >> 3;
    GemmCore gc;
    gc.A = Xh;
    gc.B = (wsel == 0) ? Wq : (wsel == 1) ? Wk : Wv;
    gc.rowBase = blockIdx.y * 128;
    gc.colBase = (ct & 7) * 128;
    gc.K = HID;
    gc.sA[0] = sptr(smem);            gc.sA[1] = sptr(smem + 36864);
    gc.sB[0] = sptr(smem + 18432);    gc.sB[1] = sptr(smem + 55296);
    gc.tid = threadIdx.x;
    gc.lane = gc.tid & 31;
    gc.w = gc.tid >> 5;
    gc.wm = gc.w & 3;
    gc.wn = gc.w >> 2;

    float acc[16][4];
#pragma unroll
    for (int i = 0; i < 16; i++)
#pragma unroll
        for (int j = 0; j < 4; j++) acc[i][j] = 0.f;

    gc.stage(0, 0);
    CPC();
    const int NK = HID / 64;
    for (int s = 0; s < NK; s++) {
        if (s + 1 < NK) { gc.stage((s + 1) * 64, (s + 1) & 1); CPC(); CPW(1); }
        else            { CPW(0); }
        __syncthreads();
        gc.compute(s & 1, acc);
        __syncthreads();
    }

    const int g = gc.lane >> 2, q = gc.lane & 3;

    if (wsel == 2) {
        // ---- V: transpose 128x128 tile in smem, write Vt[h*64+d][s] ----
        // (pipeline smem is free after the final barrier above)
        __half* ts = (__half*)smem;   // 128 rows x 136 pitch = 34,816 B
#pragma unroll
        for (int mt = 0; mt < 2; mt++)
#pragma unroll
            for (int t = 0; t < 8; t++) {
                int r = gc.wm * 32 + mt * 16 + g;
                int c = gc.wn * 64 + t * 8 + 2 * q;
                float* d = acc[mt * 8 + t];
                *(uint32_t*)&ts[r * 136 + c] = packh2(d[0], d[1]);
                *(uint32_t*)&ts[(r + 8) * 136 + c] = packh2(d[2], d[3]);
            }
        __syncthreads();
        // write coalesced along s: 128 cols x 16 chunks of 8 halves
        for (int i = gc.tid; i < 128 * 16; i += 256) {
            int dcol = i >> 4;
            int sc = (i & 15) * 8;
            __half tmp[8];
#pragma unroll
            for (int j = 0; j < 8; j++) tmp[j] = ts[(sc + j) * 136 + dcol];
            *(uint4*)&Vt[(gc.colBase + dcol) * SEQ + gc.rowBase + sc] =
                *(uint4*)tmp;
        }
        return;
    }

    // ---- Q/K: RoPE (+ scale fold for Q), direct row-major write ----
    {
        float th[8];
#pragma unroll
        for (int t = 0; t < 4; t++)
#pragma unroll
            for (int b = 0; b < 2; b++) {
                int j = t * 8 + 2 * q + b;
                th[t * 2 + b] = expf(-(float)j * (9.210340371976184f / 32.0f));
            }
#pragma unroll
        for (int mt = 0; mt < 2; mt++) {
            int r0 = gc.rowBase + gc.wm * 32 + mt * 16 + g;
            float p0 = (float)pos[r0];
            float p1 = (float)pos[r0 + 8];
#pragma unroll
            for (int t = 0; t < 4; t++) {
#pragma unroll
                for (int jj = 0; jj < 4; jj++) {
                    float pv = (jj < 2) ? p0 : p1;
                    float sn, cs;
                    sincosf(pv * th[t * 2 + (jj & 1)], &sn, &cs);
                    float x1 = acc[mt * 8 + t][jj];
                    float x2 = acc[mt * 8 + t + 4][jj];
                    acc[mt * 8 + t][jj]     = x1 * cs - x2 * sn;
                    acc[mt * 8 + t + 4][jj] = x1 * sn + x2 * cs;
                }
            }
        }
    }
    if (wsel == 0) {   // fold attention scale * log2e into Q
#pragma unroll
        for (int i = 0; i < 16; i++)
#pragma unroll
            for (int j = 0; j < 4; j++) acc[i][j] *= SLOG2E;
    }

    __half* C = (wsel == 0) ? Qh : Kh;
#pragma unroll
    for (int mt = 0; mt < 2; mt++) {
#pragma unroll
        for (int t = 0; t < 8; t++) {
            int r0 = gc.rowBase + gc.wm * 32 + mt * 16 + g;
            int c0 = gc.colBase + gc.wn * 64 + t * 8 + 2 * q;
            float* d = acc[mt * 8 + t];
            *(uint32_t*)&C[r0 * HID + c0] = packh2(d[0], d[1]);
            *(uint32_t*)&C[(r0 + 8) * HID + c0] = packh2(d[2], d[3]);
        }
    }
}

// ---------------------------------------------------------------------------
// Output GEMM: out = C @ Wo^T + bo (f32 output).
// ---------------------------------------------------------------------------
__global__ __launch_bounds__(256, 2)
void out_gemm(const __half* __restrict__ Ch, const __half* __restrict__ Wo,
              const float* __restrict__ bias, float* __restrict__ C) {
    extern __shared__ char smem[];
    GemmCore gc;
    gc.A = Ch;
    gc.B = Wo;
    gc.rowBase = blockIdx.y * 128;
    gc.colBase = blockIdx.x * 128;
    gc.K = HID;
    gc.sA[0] = sptr(smem);            gc.sA[1] = sptr(smem + 36864);
    gc.sB[0] = sptr(smem + 18432);    gc.sB[1] = sptr(smem + 55296);
    gc.tid = threadIdx.x;
    gc.lane = gc.tid & 31;
    gc.w = gc.tid >> 5;
    gc.wm = gc.w & 3;
    gc.wn = gc.w >> 2;

    float acc[16][4];
#pragma unroll
    for (int i = 0; i < 16; i++)
#pragma unroll
        for (int j = 0; j < 4; j++) acc[i][j] = 0.f;

    gc.stage(0, 0);
    CPC();
    const int NK = HID / 64;
    for (int s = 0; s < NK; s++) {
        if (s + 1 < NK) { gc.stage((s + 1) * 64, (s + 1) & 1); CPC(); CPW(1); }
        else            { CPW(0); }
        __syncthreads();
        gc.compute(s & 1, acc);
        __syncthreads();
    }

    const int g = gc.lane >> 2, q = gc.lane & 3;
#pragma unroll
    for (int mt = 0; mt < 2; mt++) {
#pragma unroll
        for (int t = 0; t < 8; t++) {
            int r0 = gc.rowBase + gc.wm * 32 + mt * 16 + g;
            int c0 = gc.colBase + gc.wn * 64 + t * 8 + 2 * q;
            float bb0 = bias[c0], bb1 = bias[c0 + 1];
            float* d = acc[mt * 8 + t];
            *(float2*)&C[r0 * HID + c0] = make_float2(d[0] + bb0, d[1] + bb1);
            *(float2*)&C[(r0 + 8) * HID + c0] = make_float2(d[2] + bb0, d[3] + bb1);
        }
    }
}

// ---------------------------------------------------------------------------
// Causal flash attention (round 15, proven): fp16 MMA, BR=64, BC=64,
// 128 threads, double-buffered K/V, Q pre-scaled (base-2 logits),
// ex2.approx.f16x2 softmax into the PV A-fragment, packed-half2 max
// butterfly (2 shfls), conditional rescale, ones-column MMA for l.
// smem: Q 9216 + 2x(K 9216 + V[80x72] 11520) = 50,688 B -> 4 CTAs/SM.
// ---------------------------------------------------------------------------
__global__ __launch_bounds__(128, 4)
void flash_h(const __half* __restrict__ Q, const __half* __restrict__ K,
             const __half* __restrict__ Vt, __half* __restrict__ O) {
    extern __shared__ char smem[];
    const uint32_t sQ = sptr(smem);                     // 64 x 72 halves
    uint32_t sK[2] = {sQ + 9216, sQ + 29952};           // 64 x 72 each
    uint32_t sV[2] = {sQ + 18432, sQ + 39168};          // 80 x 72 each

    const int tid = threadIdx.x;
    const int lane = tid & 31;
    const int w = tid >> 5;
    const int g = lane >> 2;
    const int q = lane & 3;
    const int qb = gridDim.x - 1 - blockIdx.x;          // heavy blocks first
    const int h = blockIdx.y;
    const int qBase = qb * 64;
    const int hoff = h * HD;

    const int rA = (lane & 7) + ((lane >> 3) & 1) * 8;
    const int cA = (lane >> 4) * 8;
    const int rB = (lane & 7) + (lane >> 4) * 8;
    const int cB = ((lane >> 3) & 1) * 8;

    auto load_kv = [&](int kb, int buf) {
        const int kBase = kb * 64;
#pragma unroll
        for (int t = 0; t < 8; t++) {
            int i = tid + t * 128;
            int mat = i >> 9;
            int r = (i >> 3) & 63, ch = i & 7;
            if (mat == 0)
                CPA16(sK[buf] + (r * 72 + ch * 8) * 2,
                      &K[(kBase + r) * HID + hoff + ch * 8]);
            else
                CPA16(sV[buf] + (r * 72 + ch * 8) * 2,
                      &Vt[(h * 64 + r) * SEQ + kBase + ch * 8]);
        }
    };

    // stage Q + first K/V tile
#pragma unroll
    for (int t = 0; t < 4; t++) {
        int i = tid + t * 128;
        int r = i >> 3, ch = i & 7;
        CPA16(sQ + (r * 72 + ch * 8) * 2, &Q[(qBase + r) * HID + hoff + ch * 8]);
    }
    load_kv(0, 0);
    CPC();

    // ones-column rows (64..79) of BOTH V buffers: row 64 = 1.0, rest 0.
    {
        const __half one = __float2half(1.f);
        const __half zero = __float2half(0.f);
        for (int i = tid; i < 16 * 72; i += 128) {
            int r = 64 + i / 72, c = i % 72;
            __half v = (r == 64) ? one : zero;
            *(__half*)((char*)smem + (sV[0] - sQ) + (r * 72 + c) * 2) = v;
            *(__half*)((char*)smem + (sV[1] - sQ) + (r * 72 + c) * 2) = v;
        }
    }

    float o[8][4];
#pragma unroll
    for (int t = 0; t < 8; t++)
#pragma unroll
        for (int j = 0; j < 4; j++) o[t][j] = 0.f;
    float ol[4] = {0.f, 0.f, 0.f, 0.f};   // ones-column accumulator (l in col 64)
    float m0 = -1e30f, m1 = -1e30f;

    const int r0q = qBase + w * 16 + g;
    const int r1q = r0q + 8;

    const int nkb = qb + 1;
    for (int kb = 0; kb < nkb; kb++) {
        if (kb + 1 < nkb) { load_kv(kb + 1, (kb + 1) & 1); CPC(); CPW(1); }
        else              { CPW(0); }
        __syncthreads();   // buffer kb ready (and ones rows on kb=0)

        const int kBase = kb * 64;
        const uint32_t sk = sK[kb & 1], sv = sV[kb & 1];

        // ---- Z = (Q*c) K^T  (already base-2 logits) ----
        float sfrag[8][4];
#pragma unroll
        for (int t = 0; t < 8; t++)
#pragma unroll
            for (int j = 0; j < 4; j++) sfrag[t][j] = 0.f;

#pragma unroll
        for (int kg = 0; kg < 4; kg++) {
            uint32_t a0, a1, a2, a3;
            LDSM4(a0, a1, a2, a3, sQ + ((w * 16 + rA) * 72 + kg * 16 + cA) * 2);
#pragma unroll
            for (int p = 0; p < 4; p++) {
                uint32_t b0, b1, b2, b3;
                LDSM4(b0, b1, b2, b3, sk + ((p * 16 + rB) * 72 + kg * 16 + cB) * 2);
                mma_h(sfrag[2 * p],     a0, a1, a2, a3, b0, b1);
                mma_h(sfrag[2 * p + 1], a0, a1, a2, a3, b2, b3);
            }
        }

        // ---- causal mask on diagonal tile ----
        if (kb == qb) {
#pragma unroll
            for (int nt = 0; nt < 8; nt++) {
                int c = kBase + nt * 8 + 2 * q;
                if (c     > r0q) sfrag[nt][0] = -1e30f;
                if (c + 1 > r0q) sfrag[nt][1] = -1e30f;
                if (c     > r1q) sfrag[nt][2] = -1e30f;
                if (c + 1 > r1q) sfrag[nt][3] = -1e30f;
            }
        }

        // ---- running max: thread-local tree, then ONE packed-half2 butterfly ----
        float mx0 = -1e30f, mx1 = -1e30f;
#pragma unroll
        for (int nt = 0; nt < 8; nt++) {
            mx0 = fmaxf(mx0, fmaxf(sfrag[nt][0], sfrag[nt][1]));
            mx1 = fmaxf(mx1, fmaxf(sfrag[nt][2], sfrag[nt][3]));
        }
        {
            uint32_t u = packh2(mx0, mx1);
            __half2 hm = *reinterpret_cast<__half2*>(&u);
            uint32_t u1 = __shfl_xor_sync(0xffffffffu, u, 1);
            hm = __hmax2(hm, *reinterpret_cast<__half2*>(&u1));
            uint32_t uu = *reinterpret_cast<uint32_t*>(&hm);
            uint32_t u2 = __shfl_xor_sync(0xffffffffu, uu, 2);
            hm = __hmax2(hm, *reinterpret_cast<__half2*>(&u2));
            mx0 = __low2float(hm);
            mx1 = __high2float(hm);
        }

        float mn0 = fmaxf(m0, mx0), mn1 = fmaxf(m1, mx1);
        float al0 = exp2f(m0 - mn0), al1 = exp2f(m1 - mn1);
        m0 = mn0; m1 = mn1;

        // ---- p = 2^(z - m) via f16x2 MUFU, directly in A-fragment form ----
        uint32_t plo[8], phi[8];
#pragma unroll
        for (int nt = 0; nt < 8; nt++) {
            uint32_t zl = packh2(sfrag[nt][0] - m0, sfrag[nt][1] - m0);
            uint32_t zh = packh2(sfrag[nt][2] - m1, sfrag[nt][3] - m1);
            EX2F16X2(plo[nt], zl);
            EX2F16X2(phi[nt], zh);
        }

        // ---- rescale o/l only if some lane's max advanced ----
        bool need = (al0 < 1.0f) || (al1 < 1.0f);
        if (__any_sync(0xffffffffu, need)) {
#pragma unroll
            for (int t = 0; t < 8; t++) {
                o[t][0] *= al0; o[t][1] *= al0;
                o[t][2] *= al1; o[t][3] *= al1;
            }
            ol[0] *= al0; ol[1] *= al0; ol[2] *= al1; ol[3] *= al1;
        }

        // ---- O += P V ; l += P @ ones (Vs rows 64..79, row 64 = 1.0) ----
#pragma unroll
        for (int kg = 0; kg < 4; kg++) {
            uint32_t a0 = plo[2 * kg], a1 = phi[2 * kg];
            uint32_t a2 = plo[2 * kg + 1], a3 = phi[2 * kg + 1];
#pragma unroll
            for (int p = 0; p < 4; p++) {
                uint32_t b0, b1, b2, b3;
                LDSM4(b0, b1, b2, b3, sv + ((p * 16 + rB) * 72 + kg * 16 + cB) * 2);
                mma_h(o[2 * p],     a0, a1, a2, a3, b0, b1);
                mma_h(o[2 * p + 1], a0, a1, a2, a3, b2, b3);
            }
            {
                uint32_t b0, b1, b2, b3;
                LDSM4(b0, b1, b2, b3, sv + ((64 + rB) * 72 + kg * 16 + cB) * 2);
                mma_h(ol, a0, a1, a2, a3, b0, b1);   // col 64 = l
            }
        }
        __syncthreads();   // all reads of buffer kb done before restage (kb+2)
    }

    // ---- l lives in the q==0 lane of each quad (col 64) ----
    {
        float l0 = __shfl_sync(0xffffffffu, ol[0], lane & ~3);
        float l1 = __shfl_sync(0xffffffffu, ol[2], lane & ~3);
        float inv0 = 1.f / l0, inv1 = 1.f / l1;
#pragma unroll
        for (int t = 0; t < 8; t++) {
            int c = hoff + t * 8 + 2 * q;
            *(uint32_t*)&O[r0q * HID + c] = packh2(o[t][0] * inv0, o[t][1] * inv0);
            *(uint32_t*)&O[r1q * HID + c] = packh2(o[t][2] * inv1, o[t][3] * inv1);
        }
    }
}

// ---------------------------------------------------------------------------
// Host launcher. Inputs: 0:X 1:position_ids 2:mask(unused) 3:Wq 4:Wk 5:Wv
//                        6:Wo 7:bo ; output f32[1,4096,1024]
// ---------------------------------------------------------------------------
extern "C" void kernel_launch(void* const* d_in, const int* in_sizes, int n_in,
                              void* d_out, int out_size) {
    const float* X  = (const float*)d_in[0];
    const int* pos  = (const int*)d_in[1];
    const float* Wq = (const float*)d_in[3];
    const float* Wk = (const float*)d_in[4];
    const float* Wv = (const float*)d_in[5];
    const float* Wo = (const float*)d_in[6];
    const float* bo = (const float*)d_in[7];
    float* out = (float*)d_out;

    __half *Xh, *Wqh, *Wkh, *Wvh, *Woh, *Qh, *Kh, *Vth, *Ch;
    cudaGetSymbolAddress((void**)&Xh, g_Xh);
    cudaGetSymbolAddress((void**)&Wqh, g_Wqh);
    cudaGetSymbolAddress((void**)&Wkh, g_Wkh);
    cudaGetSymbolAddress((void**)&Wvh, g_Wvh);
    cudaGetSymbolAddress((void**)&Woh, g_Woh);
    cudaGetSymbolAddress((void**)&Qh, g_Qh);
    cudaGetSymbolAddress((void**)&Kh, g_Kh);
    cudaGetSymbolAddress((void**)&Vth, g_Vth);
    cudaGetSymbolAddress((void**)&Ch, g_Ch);

    pack_all_kernel<<<8192, 256>>>(
        (const float4*)X, Xh, (const float4*)Wq, Wqh, (const float4*)Wk, Wkh,
        (const float4*)Wv, Wvh, (const float4*)Wo, Woh);

    const int gemm_smem = 73728;
    cudaFuncSetAttribute((const void*)qkv_gemm,
                         cudaFuncAttributeMaxDynamicSharedMemorySize, gemm_smem);
    cudaFuncSetAttribute((const void*)out_gemm,
                         cudaFuncAttributeMaxDynamicSharedMemorySize, gemm_smem);

    qkv_gemm<<<dim3(24, SEQ / 128), 256, gemm_smem>>>(Xh, Wqh, Wkh, Wvh, pos,
                                                      Qh, Kh, Vth);

    const int flash_smem = 50688;
    cudaFuncSetAttribute((const void*)flash_h,
                         cudaFuncAttributeMaxDynamicSharedMemorySize, flash_smem);
    flash_h<<<dim3(SEQ / 64, NH), 128, flash_smem>>>(Qh, Kh, Vth, Ch);

    out_gemm<<<dim3(HID / 128, SEQ / 128), 256, gemm_smem>>>(Ch, Woh, bo, out);
}

// round 17
// speedup vs baseline: 1.0631x; 1.0631x over previous
#include <cuda_runtime.h>
#include <cuda_fp16.h>
#include <math.h>
#include <stdint.h>

#define SEQ 4096
#define HID 1024
#define NH  16
#define HD  64

// Scratch (allocation-free rule: __device__ globals), all fp16
__device__ __half g_Xh[SEQ * HID];
__device__ __half g_Wqh[HID * HID];
__device__ __half g_Wkh[HID * HID];
__device__ __half g_Wvh[HID * HID];
__device__ __half g_Woh[HID * HID];
__device__ __half g_Qh[SEQ * HID];
__device__ __half g_Kh[SEQ * HID];
__device__ __half g_Vth[SEQ * HID];   // per-head transposed V: [h][d][s]
__device__ __half g_Ch[SEQ * HID];

// ---------------------------------------------------------------------------
// helpers
// ---------------------------------------------------------------------------
__device__ __forceinline__ uint32_t sptr(const void* p) {
    return (uint32_t)__cvta_generic_to_shared(p);
}
#define CPA16(dst, src) \
    asm volatile("cp.async.cg.shared.global [%0], [%1], 16;" :: "r"(dst), "l"(src))
#define CPC() asm volatile("cp.async.commit_group;")
#define CPW(N) asm volatile("cp.async.wait_group %0;" :: "n"(N))

#define LDSM4(r0, r1, r2, r3, addr) \
    asm volatile("ldmatrix.sync.aligned.m8n8.x4.shared.b16 {%0,%1,%2,%3}, [%4];" \
                 : "=r"(r0), "=r"(r1), "=r"(r2), "=r"(r3) : "r"(addr))

#define EX2F16X2(d, a) \
    asm volatile("ex2.approx.f16x2 %0, %1;" : "=r"(d) : "r"(a))

__device__ __forceinline__ void mma_h(float (&d)[4], uint32_t a0, uint32_t a1,
                                      uint32_t a2, uint32_t a3,
                                      uint32_t b0, uint32_t b1) {
    asm volatile(
        "mma.sync.aligned.m16n8k16.row.col.f32.f16.f16.f32 "
        "{%0,%1,%2,%3}, {%4,%5,%6,%7}, {%8,%9}, {%0,%1,%2,%3};\n"
        : "+f"(d[0]), "+f"(d[1]), "+f"(d[2]), "+f"(d[3])
        : "r"(a0), "r"(a1), "r"(a2), "r"(a3), "r"(b0), "r"(b1));
}

__device__ __forceinline__ uint32_t packh2(float lo, float hi) {
    __half2 h = __floats2half2_rn(lo, hi);
    return *reinterpret_cast<uint32_t*>(&h);
}

// scale/log2e folded into Q at projection time: S*scale*log2e == (Q*c)K^T
#define SLOG2E 0.18033688011112042f   // 0.125 * log2(e)

// ---------------------------------------------------------------------------
// f32 -> fp16 pack, all 5 tensors in one launch.
// ---------------------------------------------------------------------------
__global__ void pack_all_kernel(const float4* __restrict__ X, __half* __restrict__ Xh,
                                const float4* __restrict__ W0, __half* __restrict__ W0h,
                                const float4* __restrict__ W1, __half* __restrict__ W1h,
                                const float4* __restrict__ W2, __half* __restrict__ W2h,
                                const float4* __restrict__ W3, __half* __restrict__ W3h) {
    int b = blockIdx.x;
    const float4* src;
    __half* dst;
    int off;
    if (b < 4096)      { src = X;  dst = Xh;  off = b * 256; }
    else if (b < 5120) { src = W0; dst = W0h; off = (b - 4096) * 256; }
    else if (b < 6144) { src = W1; dst = W1h; off = (b - 5120) * 256; }
    else if (b < 7168) { src = W2; dst = W2h; off = (b - 6144) * 256; }
    else               { src = W3; dst = W3h; off = (b - 7168) * 256; }
    int i = off + threadIdx.x;
    float4 v = src[i];
    uint2 o;
    o.x = packh2(v.x, v.y);
    o.y = packh2(v.z, v.w);
    *(uint2*)&dst[i * 4] = o;
}

// ===========================================================================
// Shared GEMM machinery (round 11, proven): BM=BN=128, BK=64 halves,
// 256 thr = 8 warps (4m x 2n), 2-stage cp.async pipeline, ldmatrix.x4.
// ===========================================================================
struct GemmCore {
    const __half* A;
    const __half* B;
    int rowBase, colBase, K;
    uint32_t sA[2], sB[2];
    int tid, lane, w, wm, wn;

    __device__ __forceinline__ void stage(int k0, int buf) {
#pragma unroll
        for (int t = 0; t < 8; t++) {
            int i = tid + t * 256;
            int mat = i >> 10;
            int r = (i >> 3) & 127;
            int ch = i & 7;
            const __half* src = mat ? &B[(colBase + r) * K + k0 + ch * 8]
                                    : &A[(rowBase + r) * K + k0 + ch * 8];
            uint32_t d = (mat ? sB[buf] : sA[buf]) + (r * 72 + ch * 8) * 2;
            CPA16(d, src);
        }
    }

    __device__ __forceinline__ void compute(int buf, float (*acc)[4]) {
        const uint32_t sa = sA[buf], sb = sB[buf];
        const int rA = (lane & 7) + ((lane >> 3) & 1) * 8;
        const int cA = (lane >> 4) * 8;
        const int rB = (lane & 7) + (lane >> 4) * 8;
        const int cB = ((lane >> 3) & 1) * 8;
#pragma unroll
        for (int kg = 0; kg < 4; kg++) {
            uint32_t a[2][4];
#pragma unroll
            for (int mt = 0; mt < 2; mt++) {
                uint32_t ad = sa + ((wm * 32 + mt * 16 + rA) * 72 + kg * 16 + cA) * 2;
                LDSM4(a[mt][0], a[mt][1], a[mt][2], a[mt][3], ad);
            }
#pragma unroll
            for (int p = 0; p < 4; p++) {
                uint32_t b0, b1, b2, b3;
                uint32_t bd = sb + ((wn * 64 + p * 16 + rB) * 72 + kg * 16 + cB) * 2;
                LDSM4(b0, b1, b2, b3, bd);
                mma_h(acc[2 * p],     a[0][0], a[0][1], a[0][2], a[0][3], b0, b1);
                mma_h(acc[2 * p + 1], a[0][0], a[0][1], a[0][2], a[0][3], b2, b3);
                mma_h(acc[8 + 2 * p],     a[1][0], a[1][1], a[1][2], a[1][3], b0, b1);
                mma_h(acc[8 + 2 * p + 1], a[1][0], a[1][1], a[1][2], a[1][3], b2, b3);
            }
        }
    }
};

// ---------------------------------------------------------------------------
// Fused QKV GEMM. grid (24, 32): ct<8 -> Q (RoPE + scale fold), ct<16 -> K
// (RoPE), else V (written TRANSPOSED per head straight to Vt[h][d][s]).
// ---------------------------------------------------------------------------
__global__ __launch_bounds__(256, 2)
void qkv_gemm(const __half* __restrict__ Xh,
              const __half* __restrict__ Wq, const __half* __restrict__ Wk,
              const __half* __restrict__ Wv, const int* __restrict__ pos,
              __half* __restrict__ Qh, __half* __restrict__ Kh,
              __half* __restrict__ Vt) {
    extern __shared__ char smem[];
    const int ct = blockIdx.x;
    const int wsel = ct >> 3;
    GemmCore gc;
    gc.A = Xh;
    gc.B = (wsel == 0) ? Wq : (wsel == 1) ? Wk : Wv;
    gc.rowBase = blockIdx.y * 128;
    gc.colBase = (ct & 7) * 128;
    gc.K = HID;
    gc.sA[0] = sptr(smem);            gc.sA[1] = sptr(smem + 36864);
    gc.sB[0] = sptr(smem + 18432);    gc.sB[1] = sptr(smem + 55296);
    gc.tid = threadIdx.x;
    gc.lane = gc.tid & 31;
    gc.w = gc.tid >> 5;
    gc.wm = gc.w & 3;
    gc.wn = gc.w >> 2;

    float acc[16][4];
#pragma unroll
    for (int i = 0; i < 16; i++)
#pragma unroll
        for (int j = 0; j < 4; j++) acc[i][j] = 0.f;

    gc.stage(0, 0);
    CPC();
    const int NK = HID / 64;
    for (int s = 0; s < NK; s++) {
        if (s + 1 < NK) { gc.stage((s + 1) * 64, (s + 1) & 1); CPC(); CPW(1); }
        else            { CPW(0); }
        __syncthreads();
        gc.compute(s & 1, acc);
        __syncthreads();
    }

    const int g = gc.lane >> 2, q = gc.lane & 3;

    if (wsel == 2) {
        // ---- V: transpose 128x128 tile in smem, write Vt[h*64+d][s] ----
        __half* ts = (__half*)smem;   // 128 rows x 136 pitch
#pragma unroll
        for (int mt = 0; mt < 2; mt++)
#pragma unroll
            for (int t = 0; t < 8; t++) {
                int r = gc.wm * 32 + mt * 16 + g;
                int c = gc.wn * 64 + t * 8 + 2 * q;
                float* d = acc[mt * 8 + t];
                *(uint32_t*)&ts[r * 136 + c] = packh2(d[0], d[1]);
                *(uint32_t*)&ts[(r + 8) * 136 + c] = packh2(d[2], d[3]);
            }
        __syncthreads();
        for (int i = gc.tid; i < 128 * 16; i += 256) {
            int dcol = i >> 4;
            int sc = (i & 15) * 8;
            __half tmp[8];
#pragma unroll
            for (int j = 0; j < 8; j++) tmp[j] = ts[(sc + j) * 136 + dcol];
            *(uint4*)&Vt[(gc.colBase + dcol) * SEQ + gc.rowBase + sc] =
                *(uint4*)tmp;
        }
        return;
    }

    // ---- Q/K: RoPE (+ scale fold for Q), direct row-major write ----
    {
        float th[8];
#pragma unroll
        for (int t = 0; t < 4; t++)
#pragma unroll
            for (int b = 0; b < 2; b++) {
                int j = t * 8 + 2 * q + b;
                th[t * 2 + b] = expf(-(float)j * (9.210340371976184f / 32.0f));
            }
#pragma unroll
        for (int mt = 0; mt < 2; mt++) {
            int r0 = gc.rowBase + gc.wm * 32 + mt * 16 + g;
            float p0 = (float)pos[r0];
            float p1 = (float)pos[r0 + 8];
#pragma unroll
            for (int t = 0; t < 4; t++) {
#pragma unroll
                for (int jj = 0; jj < 4; jj++) {
                    float pv = (jj < 2) ? p0 : p1;
                    float sn, cs;
                    sincosf(pv * th[t * 2 + (jj & 1)], &sn, &cs);
                    float x1 = acc[mt * 8 + t][jj];
                    float x2 = acc[mt * 8 + t + 4][jj];
                    acc[mt * 8 + t][jj]     = x1 * cs - x2 * sn;
                    acc[mt * 8 + t + 4][jj] = x1 * sn + x2 * cs;
                }
            }
        }
    }
    if (wsel == 0) {
#pragma unroll
        for (int i = 0; i < 16; i++)
#pragma unroll
            for (int j = 0; j < 4; j++) acc[i][j] *= SLOG2E;
    }

    __half* C = (wsel == 0) ? Qh : Kh;
#pragma unroll
    for (int mt = 0; mt < 2; mt++) {
#pragma unroll
        for (int t = 0; t < 8; t++) {
            int r0 = gc.rowBase + gc.wm * 32 + mt * 16 + g;
            int c0 = gc.colBase + gc.wn * 64 + t * 8 + 2 * q;
            float* d = acc[mt * 8 + t];
            *(uint32_t*)&C[r0 * HID + c0] = packh2(d[0], d[1]);
            *(uint32_t*)&C[(r0 + 8) * HID + c0] = packh2(d[2], d[3]);
        }
    }
}

// ---------------------------------------------------------------------------
// Output GEMM: out = C @ Wo^T + bo (f32 output).
// ---------------------------------------------------------------------------
__global__ __launch_bounds__(256, 2)
void out_gemm(const __half* __restrict__ Ch, const __half* __restrict__ Wo,
              const float* __restrict__ bias, float* __restrict__ C) {
    extern __shared__ char smem[];
    GemmCore gc;
    gc.A = Ch;
    gc.B = Wo;
    gc.rowBase = blockIdx.y * 128;
    gc.colBase = blockIdx.x * 128;
    gc.K = HID;
    gc.sA[0] = sptr(smem);            gc.sA[1] = sptr(smem + 36864);
    gc.sB[0] = sptr(smem + 18432);    gc.sB[1] = sptr(smem + 55296);
    gc.tid = threadIdx.x;
    gc.lane = gc.tid & 31;
    gc.w = gc.tid >> 5;
    gc.wm = gc.w & 3;
    gc.wn = gc.w >> 2;

    float acc[16][4];
#pragma unroll
    for (int i = 0; i < 16; i++)
#pragma unroll
        for (int j = 0; j < 4; j++) acc[i][j] = 0.f;

    gc.stage(0, 0);
    CPC();
    const int NK = HID / 64;
    for (int s = 0; s < NK; s++) {
        if (s + 1 < NK) { gc.stage((s + 1) * 64, (s + 1) & 1); CPC(); CPW(1); }
        else            { CPW(0); }
        __syncthreads();
        gc.compute(s & 1, acc);
        __syncthreads();
    }

    const int g = gc.lane >> 2, q = gc.lane & 3;
#pragma unroll
    for (int mt = 0; mt < 2; mt++) {
#pragma unroll
        for (int t = 0; t < 8; t++) {
            int r0 = gc.rowBase + gc.wm * 32 + mt * 16 + g;
            int c0 = gc.colBase + gc.wn * 64 + t * 8 + 2 * q;
            float bb0 = bias[c0], bb1 = bias[c0 + 1];
            float* d = acc[mt * 8 + t];
            *(float2*)&C[r0 * HID + c0] = make_float2(d[0] + bb0, d[1] + bb1);
            *(float2*)&C[(r0 + 8) * HID + c0] = make_float2(d[2] + bb0, d[3] + bb1);
        }
    }
}

// ---------------------------------------------------------------------------
// Causal flash attention (round 15 core, proven): fp16 MMA, BR=64, BC=64,
// 128 threads, double-buffered K/V, Q pre-scaled (base-2 logits),
// ex2.approx.f16x2 softmax into PV A-frag, packed-half2 max butterfly,
// conditional rescale, ones-column MMA for l.
// NEW: diagonal-paired schedule. grid (32, 16); CTA i processes query blocks
// {63-i, i} sequentially -> every CTA does exactly 65 K-tiles. 512 CTAs =
// one perfectly balanced wave over 592 slots (was 1024 variable CTAs with a
// 64-tile critical path + wave-2 slop).
// smem: Q 9216 + 2x(K 9216 + V[80x72] 11520) = 50,688 B -> 4 CTAs/SM.
// ---------------------------------------------------------------------------
__global__ __launch_bounds__(128, 4)
void flash_h(const __half* __restrict__ Q, const __half* __restrict__ K,
             const __half* __restrict__ Vt, __half* __restrict__ O) {
    extern __shared__ char smem[];
    const uint32_t sQ = sptr(smem);                     // 64 x 72 halves
    uint32_t sK[2] = {sQ + 9216, sQ + 29952};           // 64 x 72 each
    uint32_t sV[2] = {sQ + 18432, sQ + 39168};          // 80 x 72 each

    const int tid = threadIdx.x;
    const int lane = tid & 31;
    const int w = tid >> 5;
    const int g = lane >> 2;
    const int q = lane & 3;
    const int h = blockIdx.y;
    const int hoff = h * HD;

    const int rA = (lane & 7) + ((lane >> 3) & 1) * 8;
    const int cA = (lane >> 4) * 8;
    const int rB = (lane & 7) + (lane >> 4) * 8;
    const int cB = ((lane >> 3) & 1) * 8;

    auto load_kv = [&](int kb, int buf) {
        const int kBase = kb * 64;
#pragma unroll
        for (int t = 0; t < 8; t++) {
            int i = tid + t * 128;
            int mat = i >> 9;
            int r = (i >> 3) & 63, ch = i & 7;
            if (mat == 0)
                CPA16(sK[buf] + (r * 72 + ch * 8) * 2,
                      &K[(kBase + r) * HID + hoff + ch * 8]);
            else
                CPA16(sV[buf] + (r * 72 + ch * 8) * 2,
                      &Vt[(h * 64 + r) * SEQ + kBase + ch * 8]);
        }
    };

    // ones-column rows (64..79) of BOTH V buffers: row 64 = 1.0, rest 0.
    // Written once; staging never touches rows >= 64.
    {
        const __half one = __float2half(1.f);
        const __half zero = __float2half(0.f);
        for (int i = tid; i < 16 * 72; i += 128) {
            int r = 64 + i / 72, c = i % 72;
            __half v = (r == 64) ? one : zero;
            *(__half*)((char*)smem + (sV[0] - sQ) + (r * 72 + c) * 2) = v;
            *(__half*)((char*)smem + (sV[1] - sQ) + (r * 72 + c) * 2) = v;
        }
    }

#pragma unroll 1
    for (int ph = 0; ph < 2; ph++) {
        const int qb = ph ? (int)blockIdx.x : (63 - (int)blockIdx.x);
        const int qBase = qb * 64;
        const int r0q = qBase + w * 16 + g;
        const int r1q = r0q + 8;

        // stage Q + first K/V tile for this block
#pragma unroll
        for (int t = 0; t < 4; t++) {
            int i = tid + t * 128;
            int r = i >> 3, ch = i & 7;
            CPA16(sQ + (r * 72 + ch * 8) * 2,
                  &Q[(qBase + r) * HID + hoff + ch * 8]);
        }
        load_kv(0, 0);
        CPC();

        float o[8][4];
#pragma unroll
        for (int t = 0; t < 8; t++)
#pragma unroll
            for (int j = 0; j < 4; j++) o[t][j] = 0.f;
        float ol[4] = {0.f, 0.f, 0.f, 0.f};
        float m0 = -1e30f, m1 = -1e30f;

        const int nkb = qb + 1;
        for (int kb = 0; kb < nkb; kb++) {
            if (kb + 1 < nkb) { load_kv(kb + 1, (kb + 1) & 1); CPC(); CPW(1); }
            else              { CPW(0); }
            __syncthreads();   // buffer kb (and Q on kb=0) ready

            const int kBase = kb * 64;
            const uint32_t sk = sK[kb & 1], sv = sV[kb & 1];

            // ---- Z = (Q*c) K^T ----
            float sfrag[8][4];
#pragma unroll
            for (int t = 0; t < 8; t++)
#pragma unroll
                for (int j = 0; j < 4; j++) sfrag[t][j] = 0.f;

#pragma unroll
            for (int kg = 0; kg < 4; kg++) {
                uint32_t a0, a1, a2, a3;
                LDSM4(a0, a1, a2, a3, sQ + ((w * 16 + rA) * 72 + kg * 16 + cA) * 2);
#pragma unroll
                for (int p = 0; p < 4; p++) {
                    uint32_t b0, b1, b2, b3;
                    LDSM4(b0, b1, b2, b3, sk + ((p * 16 + rB) * 72 + kg * 16 + cB) * 2);
                    mma_h(sfrag[2 * p],     a0, a1, a2, a3, b0, b1);
                    mma_h(sfrag[2 * p + 1], a0, a1, a2, a3, b2, b3);
                }
            }

            // ---- causal mask on diagonal tile ----
            if (kb == qb) {
#pragma unroll
                for (int nt = 0; nt < 8; nt++) {
                    int c = kBase + nt * 8 + 2 * q;
                    if (c     > r0q) sfrag[nt][0] = -1e30f;
                    if (c + 1 > r0q) sfrag[nt][1] = -1e30f;
                    if (c     > r1q) sfrag[nt][2] = -1e30f;
                    if (c + 1 > r1q) sfrag[nt][3] = -1e30f;
                }
            }

            // ---- running max: local tree + packed-half2 butterfly ----
            float mx0 = -1e30f, mx1 = -1e30f;
#pragma unroll
            for (int nt = 0; nt < 8; nt++) {
                mx0 = fmaxf(mx0, fmaxf(sfrag[nt][0], sfrag[nt][1]));
                mx1 = fmaxf(mx1, fmaxf(sfrag[nt][2], sfrag[nt][3]));
            }
            {
                uint32_t u = packh2(mx0, mx1);
                __half2 hm = *reinterpret_cast<__half2*>(&u);
                uint32_t u1 = __shfl_xor_sync(0xffffffffu, u, 1);
                hm = __hmax2(hm, *reinterpret_cast<__half2*>(&u1));
                uint32_t uu = *reinterpret_cast<uint32_t*>(&hm);
                uint32_t u2 = __shfl_xor_sync(0xffffffffu, uu, 2);
                hm = __hmax2(hm, *reinterpret_cast<__half2*>(&u2));
                mx0 = __low2float(hm);
                mx1 = __high2float(hm);
            }

            float mn0 = fmaxf(m0, mx0), mn1 = fmaxf(m1, mx1);
            float al0 = exp2f(m0 - mn0), al1 = exp2f(m1 - mn1);
            m0 = mn0; m1 = mn1;

            // ---- p = 2^(z - m) via f16x2 MUFU ----
            uint32_t plo[8], phi[8];
#pragma unroll
            for (int nt = 0; nt < 8; nt++) {
                uint32_t zl = packh2(sfrag[nt][0] - m0, sfrag[nt][1] - m0);
                uint32_t zh = packh2(sfrag[nt][2] - m1, sfrag[nt][3] - m1);
                EX2F16X2(plo[nt], zl);
                EX2F16X2(phi[nt], zh);
            }

            // ---- conditional rescale ----
            bool need = (al0 < 1.0f) || (al1 < 1.0f);
            if (__any_sync(0xffffffffu, need)) {
#pragma unroll
                for (int t = 0; t < 8; t++) {
                    o[t][0] *= al0; o[t][1] *= al0;
                    o[t][2] *= al1; o[t][3] *= al1;
                }
                ol[0] *= al0; ol[1] *= al0; ol[2] *= al1; ol[3] *= al1;
            }

            // ---- O += P V ; l += P @ ones ----
#pragma unroll
            for (int kg = 0; kg < 4; kg++) {
                uint32_t a0 = plo[2 * kg], a1 = phi[2 * kg];
                uint32_t a2 = plo[2 * kg + 1], a3 = phi[2 * kg + 1];
#pragma unroll
                for (int p = 0; p < 4; p++) {
                    uint32_t b0, b1, b2, b3;
                    LDSM4(b0, b1, b2, b3, sv + ((p * 16 + rB) * 72 + kg * 16 + cB) * 2);
                    mma_h(o[2 * p],     a0, a1, a2, a3, b0, b1);
                    mma_h(o[2 * p + 1], a0, a1, a2, a3, b2, b3);
                }
                {
                    uint32_t b0, b1, b2, b3;
                    LDSM4(b0, b1, b2, b3, sv + ((64 + rB) * 72 + kg * 16 + cB) * 2);
                    mma_h(ol, a0, a1, a2, a3, b0, b1);
                }
            }
            __syncthreads();   // reads of buffer kb (and sQ on last tile) done
        }

        // ---- normalize + write fp16 output for this block ----
        {
            float l0 = __shfl_sync(0xffffffffu, ol[0], lane & ~3);
            float l1 = __shfl_sync(0xffffffffu, ol[2], lane & ~3);
            float inv0 = 1.f / l0, inv1 = 1.f / l1;
#pragma unroll
            for (int t = 0; t < 8; t++) {
                int c = hoff + t * 8 + 2 * q;
                *(uint32_t*)&O[r0q * HID + c] = packh2(o[t][0] * inv0, o[t][1] * inv0);
                *(uint32_t*)&O[r1q * HID + c] = packh2(o[t][2] * inv1, o[t][3] * inv1);
            }
        }
    }
}

// ---------------------------------------------------------------------------
// Host launcher. Inputs: 0:X 1:position_ids 2:mask(unused) 3:Wq 4:Wk 5:Wv
//                        6:Wo 7:bo ; output f32[1,4096,1024]
// ---------------------------------------------------------------------------
extern "C" void kernel_launch(void* const* d_in, const int* in_sizes, int n_in,
                              void* d_out, int out_size) {
    const float* X  = (const float*)d_in[0];
    const int* pos  = (const int*)d_in[1];
    const float* Wq = (const float*)d_in[3];
    const float* Wk = (const float*)d_in[4];
    const float* Wv = (const float*)d_in[5];
    const float* Wo = (const float*)d_in[6];
    const float* bo = (const float*)d_in[7];
    float* out = (float*)d_out;

    __half *Xh, *Wqh, *Wkh, *Wvh, *Woh, *Qh, *Kh, *Vth, *Ch;
    cudaGetSymbolAddress((void**)&Xh, g_Xh);
    cudaGetSymbolAddress((void**)&Wqh, g_Wqh);
    cudaGetSymbolAddress((void**)&Wkh, g_Wkh);
    cudaGetSymbolAddress((void**)&Wvh, g_Wvh);
    cudaGetSymbolAddress((void**)&Woh, g_Woh);
    cudaGetSymbolAddress((void**)&Qh, g_Qh);
    cudaGetSymbolAddress((void**)&Kh, g_Kh);
    cudaGetSymbolAddress((void**)&Vth, g_Vth);
    cudaGetSymbolAddress((void**)&Ch, g_Ch);

    pack_all_kernel<<<8192, 256>>>(
        (const float4*)X, Xh, (const float4*)Wq, Wqh, (const float4*)Wk, Wkh,
        (const float4*)Wv, Wvh, (const float4*)Wo, Woh);

    const int gemm_smem = 73728;
    cudaFuncSetAttribute((const void*)qkv_gemm,
                         cudaFuncAttributeMaxDynamicSharedMemorySize, gemm_smem);
    cudaFuncSetAttribute((const void*)out_gemm,
                         cudaFuncAttributeMaxDynamicSharedMemorySize, gemm_smem);

    qkv_gemm<<<dim3(24, SEQ / 128), 256, gemm_smem>>>(Xh, Wqh, Wkh, Wvh, pos,
                                                      Qh, Kh, Vth);

    const int flash_smem = 50688;
    cudaFuncSetAttribute((const void*)flash_h,
                         cudaFuncAttributeMaxDynamicSharedMemorySize, flash_smem);
    flash_h<<<dim3(SEQ / 128, NH), 128, flash_smem>>>(Qh, Kh, Vth, Ch);

    out_gemm<<<dim3(HID / 128, SEQ / 128), 256, gemm_smem>>>(Ch, Woh, bo, out);
}